// round 11
// baseline (speedup 1.0000x reference)
#include <cuda_runtime.h>
#include <cuda_bf16.h>
#include <math.h>
#include <stdint.h>

// ---------------- problem constants ------------------------------------------
#define NMAX   100000
#define EMAX   3200000
#define ETOTMAX (EMAX + NMAX)
#define HC     32          // H*C

// ---------------- scratch (device globals: allocation-free rule) -------------
__device__ __align__(128) float g_xl [NMAX * HC];
__device__ __align__(128) float g_xr [NMAX * HC];
__device__ __align__(128) float g_h  [NMAX * HC];
__device__ __align__(128) int   g_src[ETOTMAX];
__device__ __align__(128) int   g_dst[ETOTMAX];
__device__ __align__(128) int   g_csrc[ETOTMAX];   // CSR: src ids sorted by dst
__device__ __align__(128) int   g_cnt[NMAX];
__device__ __align__(128) int   g_rp [NMAX + 1];   // CSR row pointers
__device__ __align__(128) int   g_pos[NMAX];       // scatter cursors
__device__ int g_i32flag;   // 1 if edge_index delivered as int32, 0 if int64

// ---------------- small helpers ------------------------------------------------
// split (v0, v1) into packed bf16x2 hi and lo parts (low half = v0)
__device__ __forceinline__ void bsplit2(float v0, float v1, uint32_t& hi, uint32_t& lo) {
    __nv_bfloat162 h = __floats2bfloat162_rn(v0, v1);
    float2 hf = __bfloat1622float2(h);
    __nv_bfloat162 l = __floats2bfloat162_rn(v0 - hf.x, v1 - hf.y);
    hi = *reinterpret_cast<uint32_t*>(&h);
    lo = *reinterpret_cast<uint32_t*>(&l);
}
#define MMA_BF16(c, a, b) \
    asm("mma.sync.aligned.m16n8k16.row.col.f32.bf16.bf16.f32 " \
        "{%0,%1,%2,%3}, {%4,%5,%6,%7}, {%8,%9}, {%0,%1,%2,%3};" \
        : "+f"((c)[0]), "+f"((c)[1]), "+f"((c)[2]), "+f"((c)[3]) \
        : "r"((a)[0]), "r"((a)[1]), "r"((a)[2]), "r"((a)[3]), \
          "r"((b)[0]), "r"((b)[1]))

// ---------------- init: zero histogram + reset dtype flag ---------------------
__global__ void k_init0(int n) {
    int i = blockIdx.x * blockDim.x + threadIdx.x;
    if (i < n) g_cnt[i] = 0;
    if (i == 0) g_i32flag = 0;
}

__global__ void k_detect(const int* __restrict__ w, int E) {
    long long i = (long long)blockIdx.x * blockDim.x + threadIdx.x;
    if (i >= E) return;
    if (w[2 * i + 1] != 0) g_i32flag = 1;     // benign race
}

// ---------------- edge decode + histogram (fused) ------------------------------
__global__ void k_prep_hist(const void* __restrict__ eiv, int E, int n) {
    int i = blockIdx.x * blockDim.x + threadIdx.x;
    int etot = E + n;
    if (i >= etot) return;
    int s, d;
    if (i < E) {
        if (g_i32flag) {
            const int* ei = (const int*)eiv;
            s = ei[i]; d = ei[(size_t)E + i];
        } else {
            const long long* ei = (const long long*)eiv;
            s = (int)ei[i]; d = (int)ei[(size_t)E + i];
        }
        s = min(max(s, 0), n - 1);
        d = min(max(d, 0), n - 1);
    } else {
        s = i - E; d = i - E;
    }
    g_src[i] = s;
    g_dst[i] = d;
    atomicAdd(&g_cnt[d], 1);
}

// ---------------- scan + scatter (counting sort by dst) ------------------------
__device__ __align__(128) int g_blk[128];
__global__ __launch_bounds__(1024) void k_scan1(int n) {
    __shared__ int sh[1024];
    int i = blockIdx.x * 1024 + threadIdx.x;
    int v = (i < n) ? g_cnt[i] : 0;
    sh[threadIdx.x] = v;
    __syncthreads();
#pragma unroll
    for (int o = 1; o < 1024; o <<= 1) {
        int t = (threadIdx.x >= o) ? sh[threadIdx.x - o] : 0;
        __syncthreads();
        sh[threadIdx.x] += t;
        __syncthreads();
    }
    if (i < n) g_rp[i] = sh[threadIdx.x] - v;   // exclusive
    if (threadIdx.x == 1023) g_blk[blockIdx.x] = sh[1023];
}
__global__ void k_scan2(int nb) {
    if (threadIdx.x == 0 && blockIdx.x == 0) {
        int run = 0;
        for (int b = 0; b < nb; b++) { int t = g_blk[b]; g_blk[b] = run; run += t; }
    }
}
__global__ void k_scan3(int n, int etot) {
    int i = blockIdx.x * blockDim.x + threadIdx.x;
    if (i < n) {
        int v = g_rp[i] + g_blk[i >> 10];
        g_rp[i] = v;
        g_pos[i] = v;
    }
    if (i == 0) g_rp[n] = etot;
}
__global__ void k_scatter(int etot) {
    int i = blockIdx.x * blockDim.x + threadIdx.x;
    if (i >= etot) return;
    int p = atomicAdd(&g_pos[g_dst[i]], 1);
    g_csrc[p] = g_src[i];
}

// ---------------- big fused GEMM  x @ [Wl | Wr] -> xl, xr  (BF16 tensor) -------
// 256 threads = 8 warps (4x2). BM=128, BN=64, BK=16. Warp tile 32x32.
// 2-way bf16 split, 3 terms (hi*hi + hi*lo + lo*hi); split done at smem-store
// time into PACKED bf16x2 tiles, so compute loop is pure LDS + MMA.
#define XPAD2 136
#define WPAD2 72
__global__ __launch_bounds__(256) void k_gemm1(
    const float* __restrict__ x, const float* __restrict__ Wl,
    const float* __restrict__ Wr, int n, int K)
{
    // packed bf16x2 tiles: [k/2][row or col], low half = even k
    __shared__ uint32_t Xh[2][8][XPAD2], Xlo[2][8][XPAD2];
    __shared__ uint32_t Wh[2][8][WPAD2], Wlo[2][8][WPAD2];

    const int tid = threadIdx.x;
    const int lane = tid & 31;
    const int warp = tid >> 5;
    const int gid = lane >> 2;        // 0..7
    const int tig = lane & 3;         // 0..3
    const int warp_row = warp & 3;    // 0..3 (32 rows each)
    const int warp_col = warp >> 2;   // 0..1 (32 cols each)
    const int r0w = warp_row * 32;
    const int wc0 = warp_col * 32;
    const int row0 = blockIdx.x * 128;

    float acc[2][4][4];
#pragma unroll
    for (int mt = 0; mt < 2; mt++)
#pragma unroll
        for (int nt = 0; nt < 4; nt++)
#pragma unroll
            for (int q = 0; q < 4; q++) acc[mt][nt][q] = 0.0f;

    // ---- X loader roles: 2 rows per thread, 4 consecutive k -------------------
    const int xr1 = tid >> 2;               // 0..63
    const int xr2 = xr1 + 64;               // 64..127
    const int xkq = (tid & 3) * 4;          // k offset within chunk: 0,4,8,12
    const int xk2 = xkq >> 1;               // k-pair index: 0,2,4,6
    int gr1 = row0 + xr1; if (gr1 >= n) gr1 = n - 1;
    int gr2 = row0 + xr2; if (gr2 >= n) gr2 = n - 1;
    const float* xp1 = x + (size_t)gr1 * K + xkq;
    const float* xp2 = x + (size_t)gr2 * K + xkq;

    // ---- W loader roles: 1 k-pair, 2 cols per thread --------------------------
    const int wk2 = tid >> 5;               // 0..7  (k pair: 2wk2, 2wk2+1)
    const int wcp = tid & 31;               // col pair: cols 2wcp, 2wcp+1
    const float* wsrc = (wcp < 16) ? Wl : Wr;
    const int wc_l = (2 * wcp) & 31;        // local col (both cols same matrix)

    const int nch = (K + 15) >> 4;

    float xreg[2][4];
    float wv[4];                            // [k-even c0, k-odd c0, k-even c1, k-odd c1]

    // ---- prefetch chunk 0
#pragma unroll
    for (int q = 0; q < 4; q++) {
        xreg[0][q] = (xkq + q < K) ? xp1[q] : 0.0f;
        xreg[1][q] = (xkq + q < K) ? xp2[q] : 0.0f;
    }
    {
        int ke = 2 * wk2, ko = ke + 1;
        wv[0] = (ke < K) ? wsrc[(size_t)ke * HC + wc_l] : 0.0f;
        wv[1] = (ko < K) ? wsrc[(size_t)ko * HC + wc_l] : 0.0f;
        wv[2] = (ke < K) ? wsrc[(size_t)ke * HC + wc_l + 1] : 0.0f;
        wv[3] = (ko < K) ? wsrc[(size_t)ko * HC + wc_l + 1] : 0.0f;
    }
    // ---- split + store buf 0
    {
        uint32_t h, l;
        bsplit2(xreg[0][0], xreg[0][1], h, l); Xh[0][xk2][xr1] = h; Xlo[0][xk2][xr1] = l;
        bsplit2(xreg[0][2], xreg[0][3], h, l); Xh[0][xk2 + 1][xr1] = h; Xlo[0][xk2 + 1][xr1] = l;
        bsplit2(xreg[1][0], xreg[1][1], h, l); Xh[0][xk2][xr2] = h; Xlo[0][xk2][xr2] = l;
        bsplit2(xreg[1][2], xreg[1][3], h, l); Xh[0][xk2 + 1][xr2] = h; Xlo[0][xk2 + 1][xr2] = l;
        bsplit2(wv[0], wv[1], h, l); Wh[0][wk2][2 * wcp] = h; Wlo[0][wk2][2 * wcp] = l;
        bsplit2(wv[2], wv[3], h, l); Wh[0][wk2][2 * wcp + 1] = h; Wlo[0][wk2][2 * wcp + 1] = l;
    }
    __syncthreads();

    for (int c = 0; c < nch; c++) {
        const int buf = c & 1;
        const int k0n = (c + 1) * 16;
        const bool more = (c + 1 < nch);

        if (more) {
#pragma unroll
            for (int q = 0; q < 4; q++) {
                int gk = k0n + xkq + q;
                xreg[0][q] = (gk < K) ? xp1[k0n + q] : 0.0f;
                xreg[1][q] = (gk < K) ? xp2[k0n + q] : 0.0f;
            }
            int ke = k0n + 2 * wk2, ko = ke + 1;
            wv[0] = (ke < K) ? wsrc[(size_t)ke * HC + wc_l] : 0.0f;
            wv[1] = (ko < K) ? wsrc[(size_t)ko * HC + wc_l] : 0.0f;
            wv[2] = (ke < K) ? wsrc[(size_t)ke * HC + wc_l + 1] : 0.0f;
            wv[3] = (ko < K) ? wsrc[(size_t)ko * HC + wc_l + 1] : 0.0f;
        }

        // ---- compute: one k16 step, pure LDS + MMA
        {
            uint32_t bh[4][2], bl[4][2];
#pragma unroll
            for (int nt = 0; nt < 4; nt++) {
                int cidx = wc0 + nt * 8 + gid;
                bh[nt][0] = Wh[buf][tig][cidx];
                bh[nt][1] = Wh[buf][tig + 4][cidx];
                bl[nt][0] = Wlo[buf][tig][cidx];
                bl[nt][1] = Wlo[buf][tig + 4][cidx];
            }
#pragma unroll
            for (int mt = 0; mt < 2; mt++) {
                int ridx = r0w + mt * 16 + gid;
                uint32_t ah[4], al[4];
                ah[0] = Xh[buf][tig][ridx];
                ah[1] = Xh[buf][tig][ridx + 8];
                ah[2] = Xh[buf][tig + 4][ridx];
                ah[3] = Xh[buf][tig + 4][ridx + 8];
                al[0] = Xlo[buf][tig][ridx];
                al[1] = Xlo[buf][tig][ridx + 8];
                al[2] = Xlo[buf][tig + 4][ridx];
                al[3] = Xlo[buf][tig + 4][ridx + 8];
#pragma unroll
                for (int nt = 0; nt < 4; nt++) {
                    MMA_BF16(acc[mt][nt], ah, bh[nt]);
                    MMA_BF16(acc[mt][nt], ah, bl[nt]);
                    MMA_BF16(acc[mt][nt], al, bh[nt]);
                }
            }
        }

        if (more) {
            const int nb = buf ^ 1;
            uint32_t h, l;
            bsplit2(xreg[0][0], xreg[0][1], h, l); Xh[nb][xk2][xr1] = h; Xlo[nb][xk2][xr1] = l;
            bsplit2(xreg[0][2], xreg[0][3], h, l); Xh[nb][xk2 + 1][xr1] = h; Xlo[nb][xk2 + 1][xr1] = l;
            bsplit2(xreg[1][0], xreg[1][1], h, l); Xh[nb][xk2][xr2] = h; Xlo[nb][xk2][xr2] = l;
            bsplit2(xreg[1][2], xreg[1][3], h, l); Xh[nb][xk2 + 1][xr2] = h; Xlo[nb][xk2 + 1][xr2] = l;
            bsplit2(wv[0], wv[1], h, l); Wh[nb][wk2][2 * wcp] = h; Wlo[nb][wk2][2 * wcp] = l;
            bsplit2(wv[2], wv[3], h, l); Wh[nb][wk2][2 * wcp + 1] = h; Wlo[nb][wk2][2 * wcp + 1] = l;
        }
        __syncthreads();
    }

    // ---- store: warp_col 0 -> xl, 1 -> xr
    float* base = (warp_col == 0) ? g_xl : g_xr;
#pragma unroll
    for (int mt = 0; mt < 2; mt++) {
#pragma unroll
        for (int nt = 0; nt < 4; nt++) {
            int col = nt * 8 + tig * 2;
            int r = row0 + r0w + mt * 16 + gid;
            if (r < n)
                *(float2*)&base[(size_t)r * HC + col] =
                    make_float2(acc[mt][nt][0], acc[mt][nt][1]);
            int r2 = r + 8;
            if (r2 < n)
                *(float2*)&base[(size_t)r2 * HC + col] =
                    make_float2(acc[mt][nt][2], acc[mt][nt][3]);
        }
    }
}

// ---------------- per-node attention core (batched-gather, float4 lanes) -------
// warp = node; lane = eq*8 + c8. Per 32-edge block: extract all 8 source ids
// up-front, issue all 8 gather LDG.128s back-to-back (MLP=8), then pure ALU.
__device__ __forceinline__ void attn_core(int node, int lane,
                                          const float* __restrict__ att,
                                          float4& accOut, float& ssumOut)
{
    const int c8 = lane & 7;
    const int eq = lane >> 3;
    const int beg = g_rp[node], end = g_rp[node + 1];
    const float4 xr4 = *(const float4*)(g_xr + (size_t)node * HC + c8 * 4);
    const float4 a4  = *(const float4*)(att + c8 * 4);
    float4 acc = make_float4(0.f, 0.f, 0.f, 0.f);
    float ssum = 0.f;

    for (int base = beg; base < end; base += 32) {
        int idx = base + lane;
        int sl = (idx < end) ? g_csrc[idx] : 0;
        int nsteps = min(32, end - base);

        // extract all 8 source ids for this edge slot (eq)
        int sk[8];
#pragma unroll
        for (int j = 0; j < 8; j++)
            sk[j] = __shfl_sync(0xffffffffu, sl, j * 4 + eq);

        // gather all 8 rows up-front — 8 independent LDG.128 in flight
        float4 xl[8];
#pragma unroll
        for (int j = 0; j < 8; j++)
            xl[j] = __ldg((const float4*)(g_xl + (size_t)sk[j] * HC) + c8);

        // score + accumulate (pure ALU/shfl/expf)
#pragma unroll
        for (int j = 0; j < 8; j++) {
            bool valid = (j * 4 + eq) < nsteps;
            float z, p;
            z = xl[j].x + xr4.x; z = fmaxf(z, 0.2f * z); p = z * a4.x;
            z = xl[j].y + xr4.y; z = fmaxf(z, 0.2f * z); p = fmaf(z, a4.y, p);
            z = xl[j].z + xr4.z; z = fmaxf(z, 0.2f * z); p = fmaf(z, a4.z, p);
            z = xl[j].w + xr4.w; z = fmaxf(z, 0.2f * z); p = fmaf(z, a4.w, p);
            p += __shfl_xor_sync(0xffffffffu, p, 1);
            p += __shfl_xor_sync(0xffffffffu, p, 2);   // per-head score (within octet)
            float ex = valid ? __expf(p) : 0.0f;
            ssum += ex;
            acc.x = fmaf(ex, xl[j].x, acc.x);
            acc.y = fmaf(ex, xl[j].y, acc.y);
            acc.z = fmaf(ex, xl[j].z, acc.z);
            acc.w = fmaf(ex, xl[j].w, acc.w);
        }
    }
#pragma unroll
    for (int o = 8; o <= 16; o <<= 1) {
        acc.x += __shfl_xor_sync(0xffffffffu, acc.x, o);
        acc.y += __shfl_xor_sync(0xffffffffu, acc.y, o);
        acc.z += __shfl_xor_sync(0xffffffffu, acc.z, o);
        acc.w += __shfl_xor_sync(0xffffffffu, acc.w, o);
        ssum  += __shfl_xor_sync(0xffffffffu, ssum,  o);
    }
    accOut = acc;
    ssumOut = ssum;
}

// ---------------- layer 1: attention + bias + ELU -> g_h ------------------------
__global__ __launch_bounds__(256) void k_attn1(const float* __restrict__ att,
                                               const float* __restrict__ bias, int n)
{
    int w = (blockIdx.x * blockDim.x + threadIdx.x) >> 5;
    int lane = threadIdx.x & 31;
    if (w >= n) return;
    float4 acc; float ssum;
    attn_core(w, lane, att, acc, ssum);
    if (lane < 8) {
        float inv = 1.0f / (ssum + 1e-16f);
        float4 b4 = *(const float4*)(bias + lane * 4);
        float4 o;
        o.x = fmaf(acc.x, inv, b4.x); o.x = (o.x > 0.f) ? o.x : expm1f(o.x);
        o.y = fmaf(acc.y, inv, b4.y); o.y = (o.y > 0.f) ? o.y : expm1f(o.y);
        o.z = fmaf(acc.z, inv, b4.z); o.z = (o.z > 0.f) ? o.z : expm1f(o.z);
        o.w = fmaf(acc.w, inv, b4.w); o.w = (o.w > 0.f) ? o.w : expm1f(o.w);
        *(float4*)(g_h + (size_t)w * HC + lane * 4) = o;
    }
}

// ---------------- small GEMM  h @ [Wl2 | Wr2] (K=32) ----------------------------
__global__ __launch_bounds__(256) void k_gemm2(
    const float* __restrict__ Wl, const float* __restrict__ Wr, int n)
{
    __shared__ float Ws2[32 * 64];
    __shared__ float hs[4][32];
    int tid = threadIdx.x;
#pragma unroll
    for (int l = 0; l < 8; l++) {
        int id = tid + l * 256;
        int k = id >> 6, c = id & 63;
        Ws2[id] = (c < HC) ? Wl[k * HC + c] : Wr[k * HC + (c - HC)];
    }
    int node0 = blockIdx.x * 4;
    if (tid < 128) {
        int nn = node0 + (tid >> 5), k = tid & 31;
        hs[tid >> 5][k] = (nn < n) ? g_h[(size_t)nn * HC + k] : 0.0f;
    }
    __syncthreads();
    int ln = tid >> 6, c = tid & 63;
    int node = node0 + ln;
    if (node >= n) return;
    float acc = 0.0f;
#pragma unroll
    for (int k = 0; k < 32; k++) acc += hs[ln][k] * Ws2[k * 64 + c];
    if (c < HC) g_xl[(size_t)node * HC + c] = acc;
    else        g_xr[(size_t)node * HC + (c - HC)] = acc;
}

// ---------------- layer 2: attention + ELU + FC + log_softmax -> out ------------
__global__ __launch_bounds__(256) void k_attn2(const float* __restrict__ att,
                                               const float* __restrict__ bias,
                                               const float* __restrict__ fcW,
                                               const float* __restrict__ fcb,
                                               float* __restrict__ out, int n)
{
    int w = (blockIdx.x * blockDim.x + threadIdx.x) >> 5;
    int lane = threadIdx.x & 31;
    if (w >= n) return;
    float4 acc; float ssum;
    attn_core(w, lane, att, acc, ssum);

    float4 h2 = make_float4(0.f, 0.f, 0.f, 0.f);
    if (lane < 8) {
        float inv = 1.0f / (ssum + 1e-16f);
        float4 b4 = *(const float4*)(bias + lane * 4);
        h2.x = fmaf(acc.x, inv, b4.x); h2.x = (h2.x > 0.f) ? h2.x : expm1f(h2.x);
        h2.y = fmaf(acc.y, inv, b4.y); h2.y = (h2.y > 0.f) ? h2.y : expm1f(h2.y);
        h2.z = fmaf(acc.z, inv, b4.z); h2.z = (h2.z > 0.f) ? h2.z : expm1f(h2.z);
        h2.w = fmaf(acc.w, inv, b4.w); h2.w = (h2.w > 0.f) ? h2.w : expm1f(h2.w);
    }

    float lg[7];
#pragma unroll
    for (int j = 0; j < 7; j++) {
        float p = 0.0f;
        if (lane < 8) {
            const float* wp = fcW + (lane * 4) * 7 + j;
            p = h2.x * wp[0] + h2.y * wp[7] + h2.z * wp[14] + h2.w * wp[21];
        }
        p += __shfl_xor_sync(0xffffffffu, p, 1);
        p += __shfl_xor_sync(0xffffffffu, p, 2);
        p += __shfl_xor_sync(0xffffffffu, p, 4);
        lg[j] = p;
    }
    if (lane == 0) {
        float mx = -1e30f;
#pragma unroll
        for (int j = 0; j < 7; j++) { lg[j] += fcb[j]; mx = fmaxf(mx, lg[j]); }
        float ss = 0.0f;
#pragma unroll
        for (int j = 0; j < 7; j++) ss += expf(lg[j] - mx);
        float lse = mx + logf(ss);
#pragma unroll
        for (int j = 0; j < 7; j++) out[(size_t)w * 7 + j] = lg[j] - lse;
    }
}

// ---------------- launch ---------------------------------------------------------
extern "C" void kernel_launch(void* const* d_in, const int* in_sizes, int n_in,
                              void* d_out, int out_size)
{
    const float* x    = (const float*)d_in[0];
    const void*  ei   = d_in[1];
    const float* Wl1  = (const float*)d_in[2];
    const float* Wr1  = (const float*)d_in[3];
    const float* a1   = (const float*)d_in[4];
    const float* b1   = (const float*)d_in[5];
    const float* Wl2  = (const float*)d_in[6];
    const float* Wr2  = (const float*)d_in[7];
    const float* a2   = (const float*)d_in[8];
    const float* b2   = (const float*)d_in[9];
    const float* fcW  = (const float*)d_in[10];
    const float* fcb  = (const float*)d_in[11];
    float*       out  = (float*)d_out;

    const int K = in_sizes[2] / HC;          // 1433
    const int n = in_sizes[0] / K;           // 100000
    const int E = in_sizes[1] / 2;           // 3200000
    const int etot = E + n;

    const int TB = 256;
    dim3 gEdge((etot + TB - 1) / TB);
    dim3 gN((n + TB - 1) / TB);
    int nWarpBlocks = (n * 32 + TB - 1) / TB;   // one warp per node
    int nb1024 = (n + 1023) / 1024;

    // ---- one-time host objects (created on the uncaptured correctness call;
    //      reused identically on every call — no device memory involved)
    static cudaStream_t s_side = nullptr;
    static cudaEvent_t  s_fork = nullptr, s_join = nullptr;
    if (s_side == nullptr) {
        cudaStreamCreateWithFlags(&s_side, cudaStreamNonBlocking);
        cudaEventCreateWithFlags(&s_fork, cudaEventDisableTiming);
        cudaEventCreateWithFlags(&s_join, cudaEventDisableTiming);
    }

    // ---- fork: CSR build on side stream, GEMM1 on main stream (independent)
    cudaEventRecord(s_fork, 0);
    cudaStreamWaitEvent(s_side, s_fork, 0);

    k_init0<<<gN, TB, 0, s_side>>>(n);
    k_detect<<<(E + TB - 1) / TB, TB, 0, s_side>>>((const int*)ei, E);
    k_prep_hist<<<gEdge, TB, 0, s_side>>>(ei, E, n);
    k_scan1<<<nb1024, 1024, 0, s_side>>>(n);
    k_scan2<<<1, 32, 0, s_side>>>(nb1024);
    k_scan3<<<gN, TB, 0, s_side>>>(n, etot);
    k_scatter<<<gEdge, TB, 0, s_side>>>(etot);
    cudaEventRecord(s_join, s_side);

    k_gemm1<<<(n + 127) / 128, 256>>>(x, Wl1, Wr1, n, K);

    // ---- join: attention needs both GEMM1 output and the CSR
    cudaStreamWaitEvent(0, s_join, 0);

    // --- layer 1
    k_attn1<<<nWarpBlocks, TB>>>(a1, b1, n);

    // --- layer 2
    k_gemm2<<<(n + 3) / 4, 256>>>(Wl2, Wr2, n);
    k_attn2<<<nWarpBlocks, TB>>>(a2, b2, fcW, fcb, out, n);
}

// round 13
// speedup vs baseline: 1.0266x; 1.0266x over previous
#include <cuda_runtime.h>
#include <cuda_bf16.h>
#include <math.h>
#include <stdint.h>

// ---------------- problem constants ------------------------------------------
#define NMAX   100000
#define EMAX   3200000
#define ETOTMAX (EMAX + NMAX)
#define HC     32          // H*C

// ---------------- scratch (device globals: allocation-free rule) -------------
__device__ __align__(128) float g_xl [NMAX * HC];
__device__ __align__(128) float g_xr [NMAX * HC];
__device__ __align__(128) float g_h  [NMAX * HC];
__device__ __align__(128) int   g_src[ETOTMAX];
__device__ __align__(128) int   g_dst[ETOTMAX];
__device__ __align__(128) int   g_csrc[ETOTMAX];   // CSR: src ids sorted by dst
__device__ __align__(128) int   g_cnt[NMAX];
__device__ __align__(128) int   g_rp [NMAX + 1];   // CSR row pointers
__device__ __align__(128) int   g_pos[NMAX];       // scatter cursors
__device__ int g_i32flag;   // 1 if edge_index delivered as int32, 0 if int64

// ---------------- small helpers ------------------------------------------------
// split (v0, v1) into packed bf16x2 hi and lo parts (low half = v0)
__device__ __forceinline__ void bsplit2(float v0, float v1, uint32_t& hi, uint32_t& lo) {
    __nv_bfloat162 h = __floats2bfloat162_rn(v0, v1);
    float2 hf = __bfloat1622float2(h);
    __nv_bfloat162 l = __floats2bfloat162_rn(v0 - hf.x, v1 - hf.y);
    hi = *reinterpret_cast<uint32_t*>(&h);
    lo = *reinterpret_cast<uint32_t*>(&l);
}
#define MMA_BF16(c, a, b) \
    asm("mma.sync.aligned.m16n8k16.row.col.f32.bf16.bf16.f32 " \
        "{%0,%1,%2,%3}, {%4,%5,%6,%7}, {%8,%9}, {%0,%1,%2,%3};" \
        : "+f"((c)[0]), "+f"((c)[1]), "+f"((c)[2]), "+f"((c)[3]) \
        : "r"((a)[0]), "r"((a)[1]), "r"((a)[2]), "r"((a)[3]), \
          "r"((b)[0]), "r"((b)[1]))

// ---------------- init: zero histogram + reset dtype flag ---------------------
__global__ void k_init0(int n) {
    int i = blockIdx.x * blockDim.x + threadIdx.x;
    if (i < n) g_cnt[i] = 0;
    if (i == 0) g_i32flag = 0;
}

__global__ void k_detect(const int* __restrict__ w, int E) {
    long long i = (long long)blockIdx.x * blockDim.x + threadIdx.x;
    if (i >= E) return;
    if (w[2 * i + 1] != 0) g_i32flag = 1;     // benign race
}

// ---------------- edge decode + histogram (fused) ------------------------------
__global__ void k_prep_hist(const void* __restrict__ eiv, int E, int n) {
    int i = blockIdx.x * blockDim.x + threadIdx.x;
    int etot = E + n;
    if (i >= etot) return;
    int s, d;
    if (i < E) {
        if (g_i32flag) {
            const int* ei = (const int*)eiv;
            s = ei[i]; d = ei[(size_t)E + i];
        } else {
            const long long* ei = (const long long*)eiv;
            s = (int)ei[i]; d = (int)ei[(size_t)E + i];
        }
        s = min(max(s, 0), n - 1);
        d = min(max(d, 0), n - 1);
    } else {
        s = i - E; d = i - E;
    }
    g_src[i] = s;
    g_dst[i] = d;
    atomicAdd(&g_cnt[d], 1);
}

// ---------------- scan + scatter (counting sort by dst) ------------------------
__device__ __align__(128) int g_blk[128];
__global__ __launch_bounds__(1024) void k_scan1(int n) {
    __shared__ int sh[1024];
    int i = blockIdx.x * 1024 + threadIdx.x;
    int v = (i < n) ? g_cnt[i] : 0;
    sh[threadIdx.x] = v;
    __syncthreads();
#pragma unroll
    for (int o = 1; o < 1024; o <<= 1) {
        int t = (threadIdx.x >= o) ? sh[threadIdx.x - o] : 0;
        __syncthreads();
        sh[threadIdx.x] += t;
        __syncthreads();
    }
    if (i < n) g_rp[i] = sh[threadIdx.x] - v;   // exclusive
    if (threadIdx.x == 1023) g_blk[blockIdx.x] = sh[1023];
}
__global__ void k_scan2(int nb) {
    if (threadIdx.x == 0 && blockIdx.x == 0) {
        int run = 0;
        for (int b = 0; b < nb; b++) { int t = g_blk[b]; g_blk[b] = run; run += t; }
    }
}
__global__ void k_scan3(int n, int etot) {
    int i = blockIdx.x * blockDim.x + threadIdx.x;
    if (i < n) {
        int v = g_rp[i] + g_blk[i >> 10];
        g_rp[i] = v;
        g_pos[i] = v;
    }
    if (i == 0) g_rp[n] = etot;
}
__global__ void k_scatter(int etot) {
    int i = blockIdx.x * blockDim.x + threadIdx.x;
    if (i >= etot) return;
    int p = atomicAdd(&g_pos[g_dst[i]], 1);
    g_csrc[p] = g_src[i];
}

// ---------------- big fused GEMM  x @ [Wl | Wr] -> xl, xr  (BF16 tensor) -------
// 256 threads = 8 warps (4x2). BM=128, BN=64, BK=16. Warp tile 32x32.
// 2-way bf16 split, 3 terms (hi*hi + hi*lo + lo*hi); split done at smem-store
// time into PACKED bf16x2 tiles, so compute loop is pure LDS + MMA.
#define XPAD2 136
#define WPAD2 72
__global__ __launch_bounds__(256) void k_gemm1(
    const float* __restrict__ x, const float* __restrict__ Wl,
    const float* __restrict__ Wr, int n, int K)
{
    // packed bf16x2 tiles: [k/2][row or col], low half = even k
    __shared__ uint32_t Xh[2][8][XPAD2], Xlo[2][8][XPAD2];
    __shared__ uint32_t Wh[2][8][WPAD2], Wlo[2][8][WPAD2];

    const int tid = threadIdx.x;
    const int lane = tid & 31;
    const int warp = tid >> 5;
    const int gid = lane >> 2;        // 0..7
    const int tig = lane & 3;         // 0..3
    const int warp_row = warp & 3;    // 0..3 (32 rows each)
    const int warp_col = warp >> 2;   // 0..1 (32 cols each)
    const int r0w = warp_row * 32;
    const int wc0 = warp_col * 32;
    const int row0 = blockIdx.x * 128;

    float acc[2][4][4];
#pragma unroll
    for (int mt = 0; mt < 2; mt++)
#pragma unroll
        for (int nt = 0; nt < 4; nt++)
#pragma unroll
            for (int q = 0; q < 4; q++) acc[mt][nt][q] = 0.0f;

    // ---- X loader roles: 2 rows per thread, 4 consecutive k -------------------
    const int xr1 = tid >> 2;               // 0..63
    const int xr2 = xr1 + 64;               // 64..127
    const int xkq = (tid & 3) * 4;          // k offset within chunk: 0,4,8,12
    const int xk2 = xkq >> 1;               // k-pair index: 0,2,4,6
    int gr1 = row0 + xr1; if (gr1 >= n) gr1 = n - 1;
    int gr2 = row0 + xr2; if (gr2 >= n) gr2 = n - 1;
    const float* xp1 = x + (size_t)gr1 * K + xkq;
    const float* xp2 = x + (size_t)gr2 * K + xkq;

    // ---- W loader roles: 1 k-pair, 2 cols per thread --------------------------
    const int wk2 = tid >> 5;               // 0..7  (k pair: 2wk2, 2wk2+1)
    const int wcp = tid & 31;               // col pair: cols 2wcp, 2wcp+1
    const float* wsrc = (wcp < 16) ? Wl : Wr;
    const int wc_l = (2 * wcp) & 31;        // local col (both cols same matrix)

    const int nch = (K + 15) >> 4;

    float xreg[2][4];
    float wv[4];                            // [k-even c0, k-odd c0, k-even c1, k-odd c1]

    // ---- prefetch chunk 0
#pragma unroll
    for (int q = 0; q < 4; q++) {
        xreg[0][q] = (xkq + q < K) ? xp1[q] : 0.0f;
        xreg[1][q] = (xkq + q < K) ? xp2[q] : 0.0f;
    }
    {
        int ke = 2 * wk2, ko = ke + 1;
        wv[0] = (ke < K) ? wsrc[(size_t)ke * HC + wc_l] : 0.0f;
        wv[1] = (ko < K) ? wsrc[(size_t)ko * HC + wc_l] : 0.0f;
        wv[2] = (ke < K) ? wsrc[(size_t)ke * HC + wc_l + 1] : 0.0f;
        wv[3] = (ko < K) ? wsrc[(size_t)ko * HC + wc_l + 1] : 0.0f;
    }
    // ---- split + store buf 0
    {
        uint32_t h, l;
        bsplit2(xreg[0][0], xreg[0][1], h, l); Xh[0][xk2][xr1] = h; Xlo[0][xk2][xr1] = l;
        bsplit2(xreg[0][2], xreg[0][3], h, l); Xh[0][xk2 + 1][xr1] = h; Xlo[0][xk2 + 1][xr1] = l;
        bsplit2(xreg[1][0], xreg[1][1], h, l); Xh[0][xk2][xr2] = h; Xlo[0][xk2][xr2] = l;
        bsplit2(xreg[1][2], xreg[1][3], h, l); Xh[0][xk2 + 1][xr2] = h; Xlo[0][xk2 + 1][xr2] = l;
        bsplit2(wv[0], wv[1], h, l); Wh[0][wk2][2 * wcp] = h; Wlo[0][wk2][2 * wcp] = l;
        bsplit2(wv[2], wv[3], h, l); Wh[0][wk2][2 * wcp + 1] = h; Wlo[0][wk2][2 * wcp + 1] = l;
    }
    __syncthreads();

    for (int c = 0; c < nch; c++) {
        const int buf = c & 1;
        const int k0n = (c + 1) * 16;
        const bool more = (c + 1 < nch);

        if (more) {
#pragma unroll
            for (int q = 0; q < 4; q++) {
                int gk = k0n + xkq + q;
                xreg[0][q] = (gk < K) ? xp1[k0n + q] : 0.0f;
                xreg[1][q] = (gk < K) ? xp2[k0n + q] : 0.0f;
            }
            int ke = k0n + 2 * wk2, ko = ke + 1;
            wv[0] = (ke < K) ? wsrc[(size_t)ke * HC + wc_l] : 0.0f;
            wv[1] = (ko < K) ? wsrc[(size_t)ko * HC + wc_l] : 0.0f;
            wv[2] = (ke < K) ? wsrc[(size_t)ke * HC + wc_l + 1] : 0.0f;
            wv[3] = (ko < K) ? wsrc[(size_t)ko * HC + wc_l + 1] : 0.0f;
        }

        // ---- compute: one k16 step, pure LDS + MMA
        {
            uint32_t bh[4][2], bl[4][2];
#pragma unroll
            for (int nt = 0; nt < 4; nt++) {
                int cidx = wc0 + nt * 8 + gid;
                bh[nt][0] = Wh[buf][tig][cidx];
                bh[nt][1] = Wh[buf][tig + 4][cidx];
                bl[nt][0] = Wlo[buf][tig][cidx];
                bl[nt][1] = Wlo[buf][tig + 4][cidx];
            }
#pragma unroll
            for (int mt = 0; mt < 2; mt++) {
                int ridx = r0w + mt * 16 + gid;
                uint32_t ah[4], al[4];
                ah[0] = Xh[buf][tig][ridx];
                ah[1] = Xh[buf][tig][ridx + 8];
                ah[2] = Xh[buf][tig + 4][ridx];
                ah[3] = Xh[buf][tig + 4][ridx + 8];
                al[0] = Xlo[buf][tig][ridx];
                al[1] = Xlo[buf][tig][ridx + 8];
                al[2] = Xlo[buf][tig + 4][ridx];
                al[3] = Xlo[buf][tig + 4][ridx + 8];
#pragma unroll
                for (int nt = 0; nt < 4; nt++) {
                    MMA_BF16(acc[mt][nt], ah, bh[nt]);
                    MMA_BF16(acc[mt][nt], ah, bl[nt]);
                    MMA_BF16(acc[mt][nt], al, bh[nt]);
                }
            }
        }

        if (more) {
            const int nb = buf ^ 1;
            uint32_t h, l;
            bsplit2(xreg[0][0], xreg[0][1], h, l); Xh[nb][xk2][xr1] = h; Xlo[nb][xk2][xr1] = l;
            bsplit2(xreg[0][2], xreg[0][3], h, l); Xh[nb][xk2 + 1][xr1] = h; Xlo[nb][xk2 + 1][xr1] = l;
            bsplit2(xreg[1][0], xreg[1][1], h, l); Xh[nb][xk2][xr2] = h; Xlo[nb][xk2][xr2] = l;
            bsplit2(xreg[1][2], xreg[1][3], h, l); Xh[nb][xk2 + 1][xr2] = h; Xlo[nb][xk2 + 1][xr2] = l;
            bsplit2(wv[0], wv[1], h, l); Wh[nb][wk2][2 * wcp] = h; Wlo[nb][wk2][2 * wcp] = l;
            bsplit2(wv[2], wv[3], h, l); Wh[nb][wk2][2 * wcp + 1] = h; Wlo[nb][wk2][2 * wcp + 1] = l;
        }
        __syncthreads();
    }

    // ---- store: warp_col 0 -> xl, 1 -> xr
    float* base = (warp_col == 0) ? g_xl : g_xr;
#pragma unroll
    for (int mt = 0; mt < 2; mt++) {
#pragma unroll
        for (int nt = 0; nt < 4; nt++) {
            int col = nt * 8 + tig * 2;
            int r = row0 + r0w + mt * 16 + gid;
            if (r < n)
                *(float2*)&base[(size_t)r * HC + col] =
                    make_float2(acc[mt][nt][0], acc[mt][nt][1]);
            int r2 = r + 8;
            if (r2 < n)
                *(float2*)&base[(size_t)r2 * HC + col] =
                    make_float2(acc[mt][nt][2], acc[mt][nt][3]);
        }
    }
}

// ---------------- per-node attention core (quad-edge, depth-2 pipeline) --------
// warp = node; lane = eq*8 + c8. MLP=2: next step's shfl+gather issued before
// processing the current step (nsteps is warp-uniform -> convergent shfl).
__device__ __forceinline__ void attn_core(int node, int lane,
                                          const float* __restrict__ att,
                                          float4& accOut, float& ssumOut)
{
    const int c8 = lane & 7;
    const int eq = lane >> 3;
    const int beg = g_rp[node], end = g_rp[node + 1];
    const float4 xr4 = *(const float4*)(g_xr + (size_t)node * HC + c8 * 4);
    const float4 a4  = *(const float4*)(att + c8 * 4);
    float4 acc = make_float4(0.f, 0.f, 0.f, 0.f);
    float ssum = 0.f;

    for (int base = beg; base < end; base += 32) {
        int idx = base + lane;
        int sl = (idx < end) ? g_csrc[idx] : 0;
        int nsteps = min(32, end - base);

        // prologue: gather step 0
        int sk0 = __shfl_sync(0xffffffffu, sl, eq);
        float4 cur = __ldg((const float4*)(g_xl + (size_t)sk0 * HC) + c8);

        for (int k4 = 0; k4 < nsteps; k4 += 4) {
            // prefetch step k4+4 (warp-uniform predicate)
            float4 nxt = cur;
            if (k4 + 4 < nsteps) {
                int skn = __shfl_sync(0xffffffffu, sl, k4 + 4 + eq);
                nxt = __ldg((const float4*)(g_xl + (size_t)skn * HC) + c8);
            }
            // process current step
            bool valid = (k4 + eq) < nsteps;
            float z, p;
            z = cur.x + xr4.x; z = fmaxf(z, 0.2f * z); p = z * a4.x;
            z = cur.y + xr4.y; z = fmaxf(z, 0.2f * z); p = fmaf(z, a4.y, p);
            z = cur.z + xr4.z; z = fmaxf(z, 0.2f * z); p = fmaf(z, a4.z, p);
            z = cur.w + xr4.w; z = fmaxf(z, 0.2f * z); p = fmaf(z, a4.w, p);
            p += __shfl_xor_sync(0xffffffffu, p, 1);
            p += __shfl_xor_sync(0xffffffffu, p, 2);   // per-head score (within octet)
            float ex = valid ? __expf(p) : 0.0f;
            ssum += ex;
            acc.x = fmaf(ex, cur.x, acc.x);
            acc.y = fmaf(ex, cur.y, acc.y);
            acc.z = fmaf(ex, cur.z, acc.z);
            acc.w = fmaf(ex, cur.w, acc.w);
            cur = nxt;
        }
    }
#pragma unroll
    for (int o = 8; o <= 16; o <<= 1) {
        acc.x += __shfl_xor_sync(0xffffffffu, acc.x, o);
        acc.y += __shfl_xor_sync(0xffffffffu, acc.y, o);
        acc.z += __shfl_xor_sync(0xffffffffu, acc.z, o);
        acc.w += __shfl_xor_sync(0xffffffffu, acc.w, o);
        ssum  += __shfl_xor_sync(0xffffffffu, ssum,  o);
    }
    accOut = acc;
    ssumOut = ssum;
}

// ---------------- layer 1: attention + bias + ELU -> g_h ------------------------
__global__ __launch_bounds__(256) void k_attn1(const float* __restrict__ att,
                                               const float* __restrict__ bias, int n)
{
    int w = (blockIdx.x * blockDim.x + threadIdx.x) >> 5;
    int lane = threadIdx.x & 31;
    if (w >= n) return;
    float4 acc; float ssum;
    attn_core(w, lane, att, acc, ssum);
    if (lane < 8) {
        float inv = 1.0f / (ssum + 1e-16f);
        float4 b4 = *(const float4*)(bias + lane * 4);
        float4 o;
        o.x = fmaf(acc.x, inv, b4.x); o.x = (o.x > 0.f) ? o.x : expm1f(o.x);
        o.y = fmaf(acc.y, inv, b4.y); o.y = (o.y > 0.f) ? o.y : expm1f(o.y);
        o.z = fmaf(acc.z, inv, b4.z); o.z = (o.z > 0.f) ? o.z : expm1f(o.z);
        o.w = fmaf(acc.w, inv, b4.w); o.w = (o.w > 0.f) ? o.w : expm1f(o.w);
        *(float4*)(g_h + (size_t)w * HC + lane * 4) = o;
    }
}

// ---------------- small GEMM  h @ [Wl2 | Wr2] (K=32) ----------------------------
__global__ __launch_bounds__(256) void k_gemm2(
    const float* __restrict__ Wl, const float* __restrict__ Wr, int n)
{
    __shared__ float Ws2[32 * 64];
    __shared__ float hs[4][32];
    int tid = threadIdx.x;
#pragma unroll
    for (int l = 0; l < 8; l++) {
        int id = tid + l * 256;
        int k = id >> 6, c = id & 63;
        Ws2[id] = (c < HC) ? Wl[k * HC + c] : Wr[k * HC + (c - HC)];
    }
    int node0 = blockIdx.x * 4;
    if (tid < 128) {
        int nn = node0 + (tid >> 5), k = tid & 31;
        hs[tid >> 5][k] = (nn < n) ? g_h[(size_t)nn * HC + k] : 0.0f;
    }
    __syncthreads();
    int ln = tid >> 6, c = tid & 63;
    int node = node0 + ln;
    if (node >= n) return;
    float acc = 0.0f;
#pragma unroll
    for (int k = 0; k < 32; k++) acc += hs[ln][k] * Ws2[k * 64 + c];
    if (c < HC) g_xl[(size_t)node * HC + c] = acc;
    else        g_xr[(size_t)node * HC + (c - HC)] = acc;
}

// ---------------- layer 2: attention + ELU + FC + log_softmax -> out ------------
__global__ __launch_bounds__(256) void k_attn2(const float* __restrict__ att,
                                               const float* __restrict__ bias,
                                               const float* __restrict__ fcW,
                                               const float* __restrict__ fcb,
                                               float* __restrict__ out, int n)
{
    int w = (blockIdx.x * blockDim.x + threadIdx.x) >> 5;
    int lane = threadIdx.x & 31;
    if (w >= n) return;
    float4 acc; float ssum;
    attn_core(w, lane, att, acc, ssum);

    float4 h2 = make_float4(0.f, 0.f, 0.f, 0.f);
    if (lane < 8) {
        float inv = 1.0f / (ssum + 1e-16f);
        float4 b4 = *(const float4*)(bias + lane * 4);
        h2.x = fmaf(acc.x, inv, b4.x); h2.x = (h2.x > 0.f) ? h2.x : expm1f(h2.x);
        h2.y = fmaf(acc.y, inv, b4.y); h2.y = (h2.y > 0.f) ? h2.y : expm1f(h2.y);
        h2.z = fmaf(acc.z, inv, b4.z); h2.z = (h2.z > 0.f) ? h2.z : expm1f(h2.z);
        h2.w = fmaf(acc.w, inv, b4.w); h2.w = (h2.w > 0.f) ? h2.w : expm1f(h2.w);
    }

    float lg[7];
#pragma unroll
    for (int j = 0; j < 7; j++) {
        float p = 0.0f;
        if (lane < 8) {
            const float* wp = fcW + (lane * 4) * 7 + j;
            p = h2.x * wp[0] + h2.y * wp[7] + h2.z * wp[14] + h2.w * wp[21];
        }
        p += __shfl_xor_sync(0xffffffffu, p, 1);
        p += __shfl_xor_sync(0xffffffffu, p, 2);
        p += __shfl_xor_sync(0xffffffffu, p, 4);
        lg[j] = p;
    }
    if (lane == 0) {
        float mx = -1e30f;
#pragma unroll
        for (int j = 0; j < 7; j++) { lg[j] += fcb[j]; mx = fmaxf(mx, lg[j]); }
        float ss = 0.0f;
#pragma unroll
        for (int j = 0; j < 7; j++) ss += expf(lg[j] - mx);
        float lse = mx + logf(ss);
#pragma unroll
        for (int j = 0; j < 7; j++) out[(size_t)w * 7 + j] = lg[j] - lse;
    }
}

// ---------------- launch ---------------------------------------------------------
extern "C" void kernel_launch(void* const* d_in, const int* in_sizes, int n_in,
                              void* d_out, int out_size)
{
    const float* x    = (const float*)d_in[0];
    const void*  ei   = d_in[1];
    const float* Wl1  = (const float*)d_in[2];
    const float* Wr1  = (const float*)d_in[3];
    const float* a1   = (const float*)d_in[4];
    const float* b1   = (const float*)d_in[5];
    const float* Wl2  = (const float*)d_in[6];
    const float* Wr2  = (const float*)d_in[7];
    const float* a2   = (const float*)d_in[8];
    const float* b2   = (const float*)d_in[9];
    const float* fcW  = (const float*)d_in[10];
    const float* fcb  = (const float*)d_in[11];
    float*       out  = (float*)d_out;

    const int K = in_sizes[2] / HC;          // 1433
    const int n = in_sizes[0] / K;           // 100000
    const int E = in_sizes[1] / 2;           // 3200000
    const int etot = E + n;

    const int TB = 256;
    dim3 gEdge((etot + TB - 1) / TB);
    dim3 gN((n + TB - 1) / TB);
    int nWarpBlocks = (n * 32 + TB - 1) / TB;   // one warp per node
    int nb1024 = (n + 1023) / 1024;

    // ---- one-time host objects (created on the uncaptured correctness call;
    //      reused identically on every call — no device memory involved)
    static cudaStream_t s_side = nullptr;
    static cudaEvent_t  s_fork = nullptr, s_join = nullptr;
    if (s_side == nullptr) {
        cudaStreamCreateWithFlags(&s_side, cudaStreamNonBlocking);
        cudaEventCreateWithFlags(&s_fork, cudaEventDisableTiming);
        cudaEventCreateWithFlags(&s_join, cudaEventDisableTiming);
    }

    // ---- fork: CSR build on side stream, GEMM1 on main stream (independent)
    cudaEventRecord(s_fork, 0);
    cudaStreamWaitEvent(s_side, s_fork, 0);

    k_init0<<<gN, TB, 0, s_side>>>(n);
    k_detect<<<(E + TB - 1) / TB, TB, 0, s_side>>>((const int*)ei, E);
    k_prep_hist<<<gEdge, TB, 0, s_side>>>(ei, E, n);
    k_scan1<<<nb1024, 1024, 0, s_side>>>(n);
    k_scan2<<<1, 32, 0, s_side>>>(nb1024);
    k_scan3<<<gN, TB, 0, s_side>>>(n, etot);
    k_scatter<<<gEdge, TB, 0, s_side>>>(etot);
    cudaEventRecord(s_join, s_side);

    k_gemm1<<<(n + 127) / 128, 256>>>(x, Wl1, Wr1, n, K);

    // ---- join: attention needs both GEMM1 output and the CSR
    cudaStreamWaitEvent(0, s_join, 0);

    // --- layer 1
    k_attn1<<<nWarpBlocks, TB>>>(a1, b1, n);

    // --- layer 2
    k_gemm2<<<(n + 3) / 4, 256>>>(Wl2, Wr2, n);
    k_attn2<<<nWarpBlocks, TB>>>(a2, b2, fcW, fcb, out, n);
}

// round 14
// speedup vs baseline: 1.0529x; 1.0256x over previous
#include <cuda_runtime.h>
#include <cuda_bf16.h>
#include <math.h>
#include <stdint.h>

// ---------------- problem constants ------------------------------------------
#define NMAX   100000
#define EMAX   3200000
#define ETOTMAX (EMAX + NMAX)
#define HC     32          // H*C
#define KPAIRS 720         // ceil(1433/2) padded to chunk multiple (90*8)

// ---------------- scratch (device globals: allocation-free rule) -------------
__device__ __align__(128) float    g_xl [NMAX * HC];
__device__ __align__(128) float    g_xr [NMAX * HC];
__device__ __align__(128) float    g_h  [NMAX * HC];
__device__ __align__(128) int      g_src[ETOTMAX];
__device__ __align__(128) int      g_dst[ETOTMAX];
__device__ __align__(128) int      g_csrc[ETOTMAX];  // CSR: src ids sorted by dst
__device__ __align__(128) int      g_cnt[NMAX];
__device__ __align__(128) int      g_rp [NMAX + 1];  // CSR row pointers
__device__ __align__(128) int      g_pos[NMAX];      // scatter cursors
__device__ __align__(128) uint32_t g_wh[KPAIRS * 64];  // W hi, packed bf16x2 per k-pair
__device__ __align__(128) uint32_t g_wl[KPAIRS * 64];  // W lo
__device__ int g_i32flag;   // 1 if edge_index delivered as int32, 0 if int64

// ---------------- small helpers ------------------------------------------------
// split (v0, v1) into packed bf16x2 hi and lo parts (low half = v0)
__device__ __forceinline__ void bsplit2(float v0, float v1, uint32_t& hi, uint32_t& lo) {
    __nv_bfloat162 h = __floats2bfloat162_rn(v0, v1);
    float2 hf = __bfloat1622float2(h);
    __nv_bfloat162 l = __floats2bfloat162_rn(v0 - hf.x, v1 - hf.y);
    hi = *reinterpret_cast<uint32_t*>(&h);
    lo = *reinterpret_cast<uint32_t*>(&l);
}
#define MMA_BF16(c, a, b) \
    asm("mma.sync.aligned.m16n8k16.row.col.f32.bf16.bf16.f32 " \
        "{%0,%1,%2,%3}, {%4,%5,%6,%7}, {%8,%9}, {%0,%1,%2,%3};" \
        : "+f"((c)[0]), "+f"((c)[1]), "+f"((c)[2]), "+f"((c)[3]) \
        : "r"((a)[0]), "r"((a)[1]), "r"((a)[2]), "r"((a)[3]), \
          "r"((b)[0]), "r"((b)[1]))

// ---------------- W pre-split: fp32 [K, HC] x2 -> packed bf16x2 hi/lo ----------
__global__ void k_wsplit(const float* __restrict__ Wl, const float* __restrict__ Wr,
                         int K) {
    int idx = blockIdx.x * blockDim.x + threadIdx.x;
    if (idx >= KPAIRS * 64) return;
    int kp = idx >> 6, col = idx & 63;
    const float* src = (col < HC) ? Wl : Wr;
    int c = col & (HC - 1);
    int ke = 2 * kp, ko = ke + 1;
    float v0 = (ke < K) ? src[(size_t)ke * HC + c] : 0.0f;
    float v1 = (ko < K) ? src[(size_t)ko * HC + c] : 0.0f;
    uint32_t h, l;
    bsplit2(v0, v1, h, l);
    g_wh[idx] = h;
    g_wl[idx] = l;
}

// ---------------- init: zero histogram + reset dtype flag ---------------------
__global__ void k_init0(int n) {
    int i = blockIdx.x * blockDim.x + threadIdx.x;
    if (i < n) g_cnt[i] = 0;
    if (i == 0) g_i32flag = 0;
}

__global__ void k_detect(const int* __restrict__ w, int E) {
    long long i = (long long)blockIdx.x * blockDim.x + threadIdx.x;
    if (i >= E) return;
    if (w[2 * i + 1] != 0) g_i32flag = 1;     // benign race
}

// ---------------- edge decode + histogram (fused) ------------------------------
__global__ void k_prep_hist(const void* __restrict__ eiv, int E, int n) {
    int i = blockIdx.x * blockDim.x + threadIdx.x;
    int etot = E + n;
    if (i >= etot) return;
    int s, d;
    if (i < E) {
        if (g_i32flag) {
            const int* ei = (const int*)eiv;
            s = ei[i]; d = ei[(size_t)E + i];
        } else {
            const long long* ei = (const long long*)eiv;
            s = (int)ei[i]; d = (int)ei[(size_t)E + i];
        }
        s = min(max(s, 0), n - 1);
        d = min(max(d, 0), n - 1);
    } else {
        s = i - E; d = i - E;
    }
    g_src[i] = s;
    g_dst[i] = d;
    atomicAdd(&g_cnt[d], 1);
}

// ---------------- scan + scatter (counting sort by dst) ------------------------
__device__ __align__(128) int g_blk[128];
__global__ __launch_bounds__(1024) void k_scan1(int n) {
    __shared__ int sh[1024];
    int i = blockIdx.x * 1024 + threadIdx.x;
    int v = (i < n) ? g_cnt[i] : 0;
    sh[threadIdx.x] = v;
    __syncthreads();
#pragma unroll
    for (int o = 1; o < 1024; o <<= 1) {
        int t = (threadIdx.x >= o) ? sh[threadIdx.x - o] : 0;
        __syncthreads();
        sh[threadIdx.x] += t;
        __syncthreads();
    }
    if (i < n) g_rp[i] = sh[threadIdx.x] - v;   // exclusive
    if (threadIdx.x == 1023) g_blk[blockIdx.x] = sh[1023];
}
__global__ void k_scan2(int nb) {
    if (threadIdx.x == 0 && blockIdx.x == 0) {
        int run = 0;
        for (int b = 0; b < nb; b++) { int t = g_blk[b]; g_blk[b] = run; run += t; }
    }
}
__global__ void k_scan3(int n, int etot) {
    int i = blockIdx.x * blockDim.x + threadIdx.x;
    if (i < n) {
        int v = g_rp[i] + g_blk[i >> 10];
        g_rp[i] = v;
        g_pos[i] = v;
    }
    if (i == 0) g_rp[n] = etot;
}
__global__ void k_scatter(int etot) {
    int i = blockIdx.x * blockDim.x + threadIdx.x;
    if (i >= etot) return;
    int p = atomicAdd(&g_pos[g_dst[i]], 1);
    g_csrc[p] = g_src[i];
}

// ---------------- big fused GEMM  x @ [Wl | Wr] -> xl, xr  (BF16 tensor) -------
// 256 threads = 8 warps (4x2). BM=128, BN=64, BK=16. Warp tile 32x32.
// 2-way bf16 split, 3 terms; X split at smem-store time, W pre-split globally.
#define XPAD2 136
#define WPAD2 72
__global__ __launch_bounds__(256) void k_gemm1(
    const float* __restrict__ x, int n, int K)
{
    // packed bf16x2 tiles: [k/2][row or col], low half = even k
    __shared__ uint32_t Xh[2][8][XPAD2], Xlo[2][8][XPAD2];
    __shared__ uint32_t Wh[2][8][WPAD2], Wlo[2][8][WPAD2];

    const int tid = threadIdx.x;
    const int lane = tid & 31;
    const int warp = tid >> 5;
    const int gid = lane >> 2;        // 0..7
    const int tig = lane & 3;         // 0..3
    const int warp_row = warp & 3;    // 0..3 (32 rows each)
    const int warp_col = warp >> 2;   // 0..1 (32 cols each)
    const int r0w = warp_row * 32;
    const int wc0 = warp_col * 32;
    const int row0 = blockIdx.x * 128;

    float acc[2][4][4];
#pragma unroll
    for (int mt = 0; mt < 2; mt++)
#pragma unroll
        for (int nt = 0; nt < 4; nt++)
#pragma unroll
            for (int q = 0; q < 4; q++) acc[mt][nt][q] = 0.0f;

    // ---- X loader roles: 2 rows per thread, 4 consecutive k -------------------
    const int xr1 = tid >> 2;               // 0..63
    const int xr2 = xr1 + 64;               // 64..127
    const int xkq = (tid & 3) * 4;          // k offset within chunk: 0,4,8,12
    const int xk2 = xkq >> 1;               // k-pair index: 0,2,4,6
    int gr1 = row0 + xr1; if (gr1 >= n) gr1 = n - 1;
    int gr2 = row0 + xr2; if (gr2 >= n) gr2 = n - 1;
    const float* xp1 = x + (size_t)gr1 * K + xkq;
    const float* xp2 = x + (size_t)gr2 * K + xkq;

    // ---- W loader roles: 1 k-pair, 2 cols per thread (pre-split global) -------
    const int wk2 = tid >> 5;               // 0..7  (k-pair within chunk)
    const int wcp = tid & 31;               // cols 2wcp, 2wcp+1

    const int nch = (K + 15) >> 4;

    float xreg[2][4];
    uint32_t wreg[4];                       // [h c0, h c1, l c0, l c1]

    // ---- prefetch chunk 0
#pragma unroll
    for (int q = 0; q < 4; q++) {
        xreg[0][q] = (xkq + q < K) ? xp1[q] : 0.0f;
        xreg[1][q] = (xkq + q < K) ? xp2[q] : 0.0f;
    }
    {
        int widx = wk2 * 64 + 2 * wcp;      // chunk 0: global kpair = wk2
        uint2 h2v = *(const uint2*)&g_wh[widx];
        uint2 l2v = *(const uint2*)&g_wl[widx];
        wreg[0] = h2v.x; wreg[1] = h2v.y; wreg[2] = l2v.x; wreg[3] = l2v.y;
    }
    // ---- split + store buf 0
    {
        uint32_t h, l;
        bsplit2(xreg[0][0], xreg[0][1], h, l); Xh[0][xk2][xr1] = h; Xlo[0][xk2][xr1] = l;
        bsplit2(xreg[0][2], xreg[0][3], h, l); Xh[0][xk2 + 1][xr1] = h; Xlo[0][xk2 + 1][xr1] = l;
        bsplit2(xreg[1][0], xreg[1][1], h, l); Xh[0][xk2][xr2] = h; Xlo[0][xk2][xr2] = l;
        bsplit2(xreg[1][2], xreg[1][3], h, l); Xh[0][xk2 + 1][xr2] = h; Xlo[0][xk2 + 1][xr2] = l;
        Wh[0][wk2][2 * wcp]     = wreg[0];
        Wh[0][wk2][2 * wcp + 1] = wreg[1];
        Wlo[0][wk2][2 * wcp]     = wreg[2];
        Wlo[0][wk2][2 * wcp + 1] = wreg[3];
    }
    __syncthreads();

    for (int c = 0; c < nch; c++) {
        const int buf = c & 1;
        const int k0n = (c + 1) * 16;
        const bool more = (c + 1 < nch);

        if (more) {
#pragma unroll
            for (int q = 0; q < 4; q++) {
                int gk = k0n + xkq + q;
                xreg[0][q] = (gk < K) ? xp1[k0n + q] : 0.0f;
                xreg[1][q] = (gk < K) ? xp2[k0n + q] : 0.0f;
            }
            int widx = ((c + 1) * 8 + wk2) * 64 + 2 * wcp;   // global kpair index
            uint2 h2v = *(const uint2*)&g_wh[widx];
            uint2 l2v = *(const uint2*)&g_wl[widx];
            wreg[0] = h2v.x; wreg[1] = h2v.y; wreg[2] = l2v.x; wreg[3] = l2v.y;
        }

        // ---- compute: one k16 step, pure LDS + MMA
        {
            uint32_t bh[4][2], bl[4][2];
#pragma unroll
            for (int nt = 0; nt < 4; nt++) {
                int cidx = wc0 + nt * 8 + gid;
                bh[nt][0] = Wh[buf][tig][cidx];
                bh[nt][1] = Wh[buf][tig + 4][cidx];
                bl[nt][0] = Wlo[buf][tig][cidx];
                bl[nt][1] = Wlo[buf][tig + 4][cidx];
            }
#pragma unroll
            for (int mt = 0; mt < 2; mt++) {
                int ridx = r0w + mt * 16 + gid;
                uint32_t ah[4], al[4];
                ah[0] = Xh[buf][tig][ridx];
                ah[1] = Xh[buf][tig][ridx + 8];
                ah[2] = Xh[buf][tig + 4][ridx];
                ah[3] = Xh[buf][tig + 4][ridx + 8];
                al[0] = Xlo[buf][tig][ridx];
                al[1] = Xlo[buf][tig][ridx + 8];
                al[2] = Xlo[buf][tig + 4][ridx];
                al[3] = Xlo[buf][tig + 4][ridx + 8];
#pragma unroll
                for (int nt = 0; nt < 4; nt++) {
                    MMA_BF16(acc[mt][nt], ah, bh[nt]);
                    MMA_BF16(acc[mt][nt], ah, bl[nt]);
                    MMA_BF16(acc[mt][nt], al, bh[nt]);
                }
            }
        }

        if (more) {
            const int nb = buf ^ 1;
            uint32_t h, l;
            bsplit2(xreg[0][0], xreg[0][1], h, l); Xh[nb][xk2][xr1] = h; Xlo[nb][xk2][xr1] = l;
            bsplit2(xreg[0][2], xreg[0][3], h, l); Xh[nb][xk2 + 1][xr1] = h; Xlo[nb][xk2 + 1][xr1] = l;
            bsplit2(xreg[1][0], xreg[1][1], h, l); Xh[nb][xk2][xr2] = h; Xlo[nb][xk2][xr2] = l;
            bsplit2(xreg[1][2], xreg[1][3], h, l); Xh[nb][xk2 + 1][xr2] = h; Xlo[nb][xk2 + 1][xr2] = l;
            Wh[nb][wk2][2 * wcp]     = wreg[0];
            Wh[nb][wk2][2 * wcp + 1] = wreg[1];
            Wlo[nb][wk2][2 * wcp]     = wreg[2];
            Wlo[nb][wk2][2 * wcp + 1] = wreg[3];
        }
        __syncthreads();
    }

    // ---- store: warp_col 0 -> xl, 1 -> xr
    float* base = (warp_col == 0) ? g_xl : g_xr;
#pragma unroll
    for (int mt = 0; mt < 2; mt++) {
#pragma unroll
        for (int nt = 0; nt < 4; nt++) {
            int col = nt * 8 + tig * 2;
            int r = row0 + r0w + mt * 16 + gid;
            if (r < n)
                *(float2*)&base[(size_t)r * HC + col] =
                    make_float2(acc[mt][nt][0], acc[mt][nt][1]);
            int r2 = r + 8;
            if (r2 < n)
                *(float2*)&base[(size_t)r2 * HC + col] =
                    make_float2(acc[mt][nt][2], acc[mt][nt][3]);
        }
    }
}

// ---------------- per-node attention core (quad-edge, float4 lanes) ------------
__device__ __forceinline__ void attn_core(int node, int lane,
                                          const float* __restrict__ att,
                                          float4& accOut, float& ssumOut)
{
    const int c8 = lane & 7;
    const int eq = lane >> 3;
    const int beg = g_rp[node], end = g_rp[node + 1];
    const float4 xr4 = *(const float4*)(g_xr + (size_t)node * HC + c8 * 4);
    const float4 a4  = *(const float4*)(att + c8 * 4);
    float4 acc = make_float4(0.f, 0.f, 0.f, 0.f);
    float ssum = 0.f;

    for (int base = beg; base < end; base += 32) {
        int idx = base + lane;
        int sl = (idx < end) ? g_csrc[idx] : 0;
        int nsteps = min(32, end - base);
        for (int k4 = 0; k4 < nsteps; k4 += 4) {
            int sk = __shfl_sync(0xffffffffu, sl, k4 + eq);
            bool valid = (k4 + eq) < nsteps;
            float4 xl4 = __ldg((const float4*)(g_xl + (size_t)sk * HC) + c8);
            float z, p;
            z = xl4.x + xr4.x; z = fmaxf(z, 0.2f * z); p = z * a4.x;
            z = xl4.y + xr4.y; z = fmaxf(z, 0.2f * z); p = fmaf(z, a4.y, p);
            z = xl4.z + xr4.z; z = fmaxf(z, 0.2f * z); p = fmaf(z, a4.z, p);
            z = xl4.w + xr4.w; z = fmaxf(z, 0.2f * z); p = fmaf(z, a4.w, p);
            p += __shfl_xor_sync(0xffffffffu, p, 1);
            p += __shfl_xor_sync(0xffffffffu, p, 2);   // per-head score (within octet)
            float ex = valid ? __expf(p) : 0.0f;
            ssum += ex;
            acc.x = fmaf(ex, xl4.x, acc.x);
            acc.y = fmaf(ex, xl4.y, acc.y);
            acc.z = fmaf(ex, xl4.z, acc.z);
            acc.w = fmaf(ex, xl4.w, acc.w);
        }
    }
#pragma unroll
    for (int o = 8; o <= 16; o <<= 1) {
        acc.x += __shfl_xor_sync(0xffffffffu, acc.x, o);
        acc.y += __shfl_xor_sync(0xffffffffu, acc.y, o);
        acc.z += __shfl_xor_sync(0xffffffffu, acc.z, o);
        acc.w += __shfl_xor_sync(0xffffffffu, acc.w, o);
        ssum  += __shfl_xor_sync(0xffffffffu, ssum,  o);
    }
    accOut = acc;
    ssumOut = ssum;
}

// ---------------- layer 1: attention + bias + ELU -> g_h ------------------------
__global__ __launch_bounds__(256) void k_attn1(const float* __restrict__ att,
                                               const float* __restrict__ bias, int n)
{
    int w = (blockIdx.x * blockDim.x + threadIdx.x) >> 5;
    int lane = threadIdx.x & 31;
    if (w >= n) return;
    float4 acc; float ssum;
    attn_core(w, lane, att, acc, ssum);
    if (lane < 8) {
        float inv = 1.0f / (ssum + 1e-16f);
        float4 b4 = *(const float4*)(bias + lane * 4);
        float4 o;
        o.x = fmaf(acc.x, inv, b4.x); o.x = (o.x > 0.f) ? o.x : expm1f(o.x);
        o.y = fmaf(acc.y, inv, b4.y); o.y = (o.y > 0.f) ? o.y : expm1f(o.y);
        o.z = fmaf(acc.z, inv, b4.z); o.z = (o.z > 0.f) ? o.z : expm1f(o.z);
        o.w = fmaf(acc.w, inv, b4.w); o.w = (o.w > 0.f) ? o.w : expm1f(o.w);
        *(float4*)(g_h + (size_t)w * HC + lane * 4) = o;
    }
}

// ---------------- small GEMM  h @ [Wl2 | Wr2] (K=32) ----------------------------
__global__ __launch_bounds__(256) void k_gemm2(
    const float* __restrict__ Wl, const float* __restrict__ Wr, int n)
{
    __shared__ float Ws2[32 * 64];
    __shared__ float hs[4][32];
    int tid = threadIdx.x;
#pragma unroll
    for (int l = 0; l < 8; l++) {
        int id = tid + l * 256;
        int k = id >> 6, c = id & 63;
        Ws2[id] = (c < HC) ? Wl[k * HC + c] : Wr[k * HC + (c - HC)];
    }
    int node0 = blockIdx.x * 4;
    if (tid < 128) {
        int nn = node0 + (tid >> 5), k = tid & 31;
        hs[tid >> 5][k] = (nn < n) ? g_h[(size_t)nn * HC + k] : 0.0f;
    }
    __syncthreads();
    int ln = tid >> 6, c = tid & 63;
    int node = node0 + ln;
    if (node >= n) return;
    float acc = 0.0f;
#pragma unroll
    for (int k = 0; k < 32; k++) acc += hs[ln][k] * Ws2[k * 64 + c];
    if (c < HC) g_xl[(size_t)node * HC + c] = acc;
    else        g_xr[(size_t)node * HC + (c - HC)] = acc;
}

// ---------------- layer 2: attention + ELU + FC + log_softmax -> out ------------
__global__ __launch_bounds__(256) void k_attn2(const float* __restrict__ att,
                                               const float* __restrict__ bias,
                                               const float* __restrict__ fcW,
                                               const float* __restrict__ fcb,
                                               float* __restrict__ out, int n)
{
    int w = (blockIdx.x * blockDim.x + threadIdx.x) >> 5;
    int lane = threadIdx.x & 31;
    if (w >= n) return;
    float4 acc; float ssum;
    attn_core(w, lane, att, acc, ssum);

    float4 h2 = make_float4(0.f, 0.f, 0.f, 0.f);
    if (lane < 8) {
        float inv = 1.0f / (ssum + 1e-16f);
        float4 b4 = *(const float4*)(bias + lane * 4);
        h2.x = fmaf(acc.x, inv, b4.x); h2.x = (h2.x > 0.f) ? h2.x : expm1f(h2.x);
        h2.y = fmaf(acc.y, inv, b4.y); h2.y = (h2.y > 0.f) ? h2.y : expm1f(h2.y);
        h2.z = fmaf(acc.z, inv, b4.z); h2.z = (h2.z > 0.f) ? h2.z : expm1f(h2.z);
        h2.w = fmaf(acc.w, inv, b4.w); h2.w = (h2.w > 0.f) ? h2.w : expm1f(h2.w);
    }

    float lg[7];
#pragma unroll
    for (int j = 0; j < 7; j++) {
        float p = 0.0f;
        if (lane < 8) {
            const float* wp = fcW + (lane * 4) * 7 + j;
            p = h2.x * wp[0] + h2.y * wp[7] + h2.z * wp[14] + h2.w * wp[21];
        }
        p += __shfl_xor_sync(0xffffffffu, p, 1);
        p += __shfl_xor_sync(0xffffffffu, p, 2);
        p += __shfl_xor_sync(0xffffffffu, p, 4);
        lg[j] = p;
    }
    if (lane == 0) {
        float mx = -1e30f;
#pragma unroll
        for (int j = 0; j < 7; j++) { lg[j] += fcb[j]; mx = fmaxf(mx, lg[j]); }
        float ss = 0.0f;
#pragma unroll
        for (int j = 0; j < 7; j++) ss += expf(lg[j] - mx);
        float lse = mx + logf(ss);
#pragma unroll
        for (int j = 0; j < 7; j++) out[(size_t)w * 7 + j] = lg[j] - lse;
    }
}

// ---------------- launch ---------------------------------------------------------
extern "C" void kernel_launch(void* const* d_in, const int* in_sizes, int n_in,
                              void* d_out, int out_size)
{
    const float* x    = (const float*)d_in[0];
    const void*  ei   = d_in[1];
    const float* Wl1  = (const float*)d_in[2];
    const float* Wr1  = (const float*)d_in[3];
    const float* a1   = (const float*)d_in[4];
    const float* b1   = (const float*)d_in[5];
    const float* Wl2  = (const float*)d_in[6];
    const float* Wr2  = (const float*)d_in[7];
    const float* a2   = (const float*)d_in[8];
    const float* b2   = (const float*)d_in[9];
    const float* fcW  = (const float*)d_in[10];
    const float* fcb  = (const float*)d_in[11];
    float*       out  = (float*)d_out;

    const int K = in_sizes[2] / HC;          // 1433
    const int n = in_sizes[0] / K;           // 100000
    const int E = in_sizes[1] / 2;           // 3200000
    const int etot = E + n;

    const int TB = 256;
    dim3 gEdge((etot + TB - 1) / TB);
    dim3 gN((n + TB - 1) / TB);
    int nWarpBlocks = (n * 32 + TB - 1) / TB;   // one warp per node
    int nb1024 = (n + 1023) / 1024;

    // ---- one-time host objects (created on the uncaptured correctness call)
    static cudaStream_t s_side = nullptr;
    static cudaEvent_t  s_fork = nullptr, s_join = nullptr;
    if (s_side == nullptr) {
        cudaStreamCreateWithFlags(&s_side, cudaStreamNonBlocking);
        cudaEventCreateWithFlags(&s_fork, cudaEventDisableTiming);
        cudaEventCreateWithFlags(&s_join, cudaEventDisableTiming);
    }

    // ---- fork: CSR build on side stream, GEMM path on main stream
    cudaEventRecord(s_fork, 0);
    cudaStreamWaitEvent(s_side, s_fork, 0);

    // launch order chosen so k_gemm1 is the 4th kernel launch (ncu captures #4)
    k_wsplit<<<(KPAIRS * 64 + TB - 1) / TB, TB>>>(Wl1, Wr1, K);     // 1 (main)
    k_init0<<<gN, TB, 0, s_side>>>(n);                              // 2 (side)
    k_detect<<<(E + TB - 1) / TB, TB, 0, s_side>>>((const int*)ei, E); // 3 (side)
    k_gemm1<<<(n + 127) / 128, 256>>>(x, n, K);                     // 4 (main)
    k_prep_hist<<<gEdge, TB, 0, s_side>>>(ei, E, n);                // 5 (side)
    k_scan1<<<nb1024, 1024, 0, s_side>>>(n);                        // 6
    k_scan2<<<1, 32, 0, s_side>>>(nb1024);                          // 7
    k_scan3<<<gN, TB, 0, s_side>>>(n, etot);                        // 8
    k_scatter<<<gEdge, TB, 0, s_side>>>(etot);                      // 9
    cudaEventRecord(s_join, s_side);

    // ---- join: attention needs both GEMM1 output and the CSR
    cudaStreamWaitEvent(0, s_join, 0);

    // --- layer 1
    k_attn1<<<nWarpBlocks, TB>>>(a1, b1, n);

    // --- layer 2
    k_gemm2<<<(n + 3) / 4, 256>>>(Wl2, Wr2, n);
    k_attn2<<<nWarpBlocks, TB>>>(a2, b2, fcW, fcb, out, n);
}